// round 2
// baseline (speedup 1.0000x reference)
#include <cuda_runtime.h>
#include <cstdint>
#include <cstddef>

#define NTOK   98
#define NPADK  104
#define HEADS  4
#define DIM    128
#define BATCH  4096
#define NW     64
#define SCALE  0.17677669529663687f

__device__ float g_q[(size_t)BATCH * HEADS * NTOK * 32];
__device__ float g_k[(size_t)BATCH * HEADS * NTOK * 32];
__device__ float g_v[(size_t)BATCH * HEADS * NTOK * 32];
__device__ float g_o[(size_t)BATCH * NTOK * DIM];
__device__ float g_comb[(size_t)NW * HEADS * NTOK * NPADK];

__device__ __forceinline__ float tf32r(float x) {
    unsigned u;
    asm("cvt.rna.tf32.f32 %0, %1;" : "=r"(u) : "f"(x));
    return __uint_as_float(u);
}
__device__ __forceinline__ float ex2f(float x) {
    float y;
    asm("ex2.approx.f32 %0, %1;" : "=f"(y) : "f"(x));
    return y;
}
__device__ __forceinline__ void mma8(float c[4], float a0, float a1, float a2, float a3,
                                     float b0, float b1) {
    asm volatile(
        "mma.sync.aligned.m16n8k8.row.col.f32.tf32.tf32.f32 "
        "{%0,%1,%2,%3},{%4,%5,%6,%7},{%8,%9},{%0,%1,%2,%3};\n"
        : "+f"(c[0]), "+f"(c[1]), "+f"(c[2]), "+f"(c[3])
        : "r"(__float_as_uint(a0)), "r"(__float_as_uint(a1)),
          "r"(__float_as_uint(a2)), "r"(__float_as_uint(a3)),
          "r"(__float_as_uint(b0)), "r"(__float_as_uint(b1)));
}

// ---------------- K0: comb = mask + gathered bias, padded ----------------
__global__ void k_comb(const float* __restrict__ mask,
                       const float* __restrict__ rpb,
                       const int* __restrict__ relidx) {
    const int w = blockIdx.x >> 2, h = blockIdx.x & 3;
    float* dst = g_comb + (size_t)(w * HEADS + h) * NTOK * NPADK;
    const float* msk = mask + (size_t)w * NTOK * NTOK;
    for (int idx = threadIdx.x; idx < NTOK * NPADK; idx += blockDim.x) {
        int i = idx / NPADK, j = idx - i * NPADK;
        float v = -10000.0f;
        if (j < NTOK) v = msk[i * NTOK + j] + rpb[relidx[i * NTOK + j] * HEADS + h];
        dst[idx] = v;
    }
}

// ---------------- shared GEMM body: C[128m x 128n] = A[m][128k] * W[n][128k] ----------------
struct Frag64x32 { float c[4][4][4]; };

__device__ __forceinline__ void gemm_tile(const float* __restrict__ A,
                                          const float* __restrict__ W,
                                          int m0, int n0, Frag64x32& F,
                                          float (*As)[36], float (*Bs)[36]) {
    const int tid = threadIdx.x, lane = tid & 31, warp = tid >> 5;
    const int g = lane >> 2, tg = lane & 3;
    const int wm = warp >> 2, wn = warp & 3;
    const int fi = (tid & 7) * 4, r0 = tid >> 3;
#pragma unroll
    for (int i = 0; i < 4; i++)
#pragma unroll
        for (int j = 0; j < 4; j++)
#pragma unroll
            for (int q = 0; q < 4; q++) F.c[i][j][q] = 0.f;

    for (int kk = 0; kk < 128; kk += 32) {
#pragma unroll
        for (int rr = 0; rr < 4; rr++) {
            int r = r0 + rr * 32;
            float4 va = *reinterpret_cast<const float4*>(&A[(size_t)(m0 + r) * 128 + kk + fi]);
            float4 vb = *reinterpret_cast<const float4*>(&W[(size_t)(n0 + r) * 128 + kk + fi]);
            *reinterpret_cast<float4*>(&As[r][fi]) =
                make_float4(tf32r(va.x), tf32r(va.y), tf32r(va.z), tf32r(va.w));
            *reinterpret_cast<float4*>(&Bs[r][fi]) =
                make_float4(tf32r(vb.x), tf32r(vb.y), tf32r(vb.z), tf32r(vb.w));
        }
        __syncthreads();
#pragma unroll
        for (int ks = 0; ks < 32; ks += 8) {
            float a[4][4], bb[4][2];
#pragma unroll
            for (int mi = 0; mi < 4; mi++) {
                int rr = wm * 64 + mi * 16 + g;
                a[mi][0] = As[rr][ks + tg];     a[mi][1] = As[rr + 8][ks + tg];
                a[mi][2] = As[rr][ks + tg + 4]; a[mi][3] = As[rr + 8][ks + tg + 4];
            }
#pragma unroll
            for (int ni = 0; ni < 4; ni++) {
                int cc = wn * 32 + ni * 8 + g;
                bb[ni][0] = Bs[cc][ks + tg]; bb[ni][1] = Bs[cc][ks + tg + 4];
            }
#pragma unroll
            for (int mi = 0; mi < 4; mi++)
#pragma unroll
                for (int ni = 0; ni < 4; ni++)
                    mma8(F.c[mi][ni], a[mi][0], a[mi][1], a[mi][2], a[mi][3],
                         bb[ni][0], bb[ni][1]);
        }
        __syncthreads();
    }
}

// ---------------- K1: QKV GEMM + scatter ----------------
__global__ void __launch_bounds__(256) k_qkv(const float* __restrict__ x,
                                             const float* __restrict__ w,
                                             const float* __restrict__ bias) {
    __shared__ float As[128][36];
    __shared__ float Bs[128][36];
    const int m0 = blockIdx.x * 128, n0 = blockIdx.y * 128;
    const int tid = threadIdx.x, lane = tid & 31, warp = tid >> 5;
    const int g = lane >> 2, tg = lane & 3;
    const int wm = warp >> 2, wn = warp & 3;
    Frag64x32 F;
    gemm_tile(x, w, m0, n0, F, As, Bs);
#pragma unroll
    for (int ni = 0; ni < 4; ni++) {
        int col = n0 + wn * 32 + ni * 8 + tg * 2;
        float b0 = bias[col], b1 = bias[col + 1];
        int sel = col >> 7, o = col & 127, h = o >> 5, d = o & 31;
        float* base = (sel == 0) ? g_q : ((sel == 1) ? g_k : g_v);
#pragma unroll
        for (int mi = 0; mi < 4; mi++) {
            int m = m0 + wm * 64 + mi * 16 + g;
            int b = m / NTOK, n = m - b * NTOK;
            *reinterpret_cast<float2*>(&base[(((size_t)b * HEADS + h) * NTOK + n) * 32 + d]) =
                make_float2(F.c[mi][ni][0] + b0, F.c[mi][ni][1] + b1);
            int m2 = m + 8, b2 = m2 / NTOK, n2 = m2 - b2 * NTOK;
            *reinterpret_cast<float2*>(&base[(((size_t)b2 * HEADS + h) * NTOK + n2) * 32 + d]) =
                make_float2(F.c[mi][ni][2] + b0, F.c[mi][ni][3] + b1);
        }
    }
}

// ---------------- K2: fused attention ----------------
#define SM_Q    (NTOK * NPADK)
#define SM_K    (SM_Q + 128 * 36)
#define SM_V    (SM_K + 104 * 36)
#define SM_P    (SM_V + 104 * 40)
#define ATTN_SMEM_BYTES ((SM_P + 128 * 108) * 4)

__global__ void __launch_bounds__(256) k_attn() {
    extern __shared__ float sm[];
    float* comb_s = sm;             // [98][104]
    float* q_s = sm + SM_Q;         // [128][36] pre-scaled, rows>=98 zero
    float* k_s = sm + SM_K;         // [104][36] rows>=98 zero
    float* v_s = sm + SM_V;         // [104][40] rows>=98 zero
    float* p_s = sm + SM_P;         // [128][108]

    const int t = blockIdx.x, h = blockIdx.y, w = blockIdx.z;
    const int tid = threadIdx.x, lane = tid & 31, warp = tid >> 5;
    const int g = lane >> 2, tg = lane & 3;
    const int R0 = warp * 16;
    const int r1 = R0 + g, r2 = R0 + g + 8;
    const int cr1 = min(r1, NTOK - 1), cr2 = min(r2, NTOK - 1);
    const float L2E = 1.4426950408889634f;

    {
        const float* cg = g_comb + (size_t)(w * HEADS + h) * NTOK * NPADK;
        for (int i = tid; i < NTOK * NPADK; i += 256) comb_s[i] = cg[i];
    }

    for (int jj = 0; jj < 8; jj++) {
        const int b = (t * 8 + jj) * NW + w;
        __syncthreads();
        const size_t off = ((size_t)b * HEADS + h) * NTOK * 32;
        const float* gq = g_q + off;
        const float* gk = g_k + off;
        const float* gv = g_v + off;

        for (int i = tid; i < 128 * 8; i += 256) {
            int r = i >> 3, f = (i & 7) * 4;
            float4 v4 = make_float4(0.f, 0.f, 0.f, 0.f);
            if (r < NTOK) v4 = *reinterpret_cast<const float4*>(&gq[r * 32 + f]);
            *reinterpret_cast<float4*>(&q_s[r * 36 + f]) =
                make_float4(tf32r(v4.x * SCALE), tf32r(v4.y * SCALE),
                            tf32r(v4.z * SCALE), tf32r(v4.w * SCALE));
        }
        for (int i = tid; i < 104 * 8; i += 256) {
            int r = i >> 3, f = (i & 7) * 4;
            float4 kv = make_float4(0.f, 0.f, 0.f, 0.f), vv = kv;
            if (r < NTOK) {
                kv = *reinterpret_cast<const float4*>(&gk[r * 32 + f]);
                vv = *reinterpret_cast<const float4*>(&gv[r * 32 + f]);
            }
            *reinterpret_cast<float4*>(&k_s[r * 36 + f]) =
                make_float4(tf32r(kv.x), tf32r(kv.y), tf32r(kv.z), tf32r(kv.w));
            *reinterpret_cast<float4*>(&v_s[r * 40 + f]) =
                make_float4(tf32r(vv.x), tf32r(vv.y), tf32r(vv.z), tf32r(vv.w));
        }
        __syncthreads();

        // S = (q*scale) @ k^T : warp owns 16 rows x 104 cols (13 n8 tiles)
        float s[13][4];
#pragma unroll
        for (int ni = 0; ni < 13; ni++)
            s[ni][0] = s[ni][1] = s[ni][2] = s[ni][3] = 0.f;
#pragma unroll
        for (int ks = 0; ks < 32; ks += 8) {
            float a0 = q_s[r1 * 36 + ks + tg],     a1 = q_s[r2 * 36 + ks + tg];
            float a2 = q_s[r1 * 36 + ks + tg + 4], a3 = q_s[r2 * 36 + ks + tg + 4];
#pragma unroll
            for (int ni = 0; ni < 13; ni++) {
                float b0 = k_s[(ni * 8 + g) * 36 + ks + tg];
                float b1 = k_s[(ni * 8 + g) * 36 + ks + tg + 4];
                mma8(s[ni], a0, a1, a2, a3, b0, b1);
            }
        }
        // add comb bias; softmax over the quad (4 tg threads hold a full row)
        float m1 = -1e30f, m2 = -1e30f;
#pragma unroll
        for (int ni = 0; ni < 13; ni++) {
            int c0 = ni * 8 + tg * 2;
            s[ni][0] += comb_s[cr1 * NPADK + c0];
            s[ni][1] += comb_s[cr1 * NPADK + c0 + 1];
            s[ni][2] += comb_s[cr2 * NPADK + c0];
            s[ni][3] += comb_s[cr2 * NPADK + c0 + 1];
            m1 = fmaxf(m1, fmaxf(s[ni][0], s[ni][1]));
            m2 = fmaxf(m2, fmaxf(s[ni][2], s[ni][3]));
        }
        m1 = fmaxf(m1, __shfl_xor_sync(0xffffffffu, m1, 1));
        m1 = fmaxf(m1, __shfl_xor_sync(0xffffffffu, m1, 2));
        m2 = fmaxf(m2, __shfl_xor_sync(0xffffffffu, m2, 1));
        m2 = fmaxf(m2, __shfl_xor_sync(0xffffffffu, m2, 2));
        float sum1 = 0.f, sum2 = 0.f;
#pragma unroll
        for (int ni = 0; ni < 13; ni++) {
            s[ni][0] = ex2f((s[ni][0] - m1) * L2E);
            s[ni][1] = ex2f((s[ni][1] - m1) * L2E);
            s[ni][2] = ex2f((s[ni][2] - m2) * L2E);
            s[ni][3] = ex2f((s[ni][3] - m2) * L2E);
            sum1 += s[ni][0] + s[ni][1];
            sum2 += s[ni][2] + s[ni][3];
        }
        sum1 += __shfl_xor_sync(0xffffffffu, sum1, 1);
        sum1 += __shfl_xor_sync(0xffffffffu, sum1, 2);
        sum2 += __shfl_xor_sync(0xffffffffu, sum2, 1);
        sum2 += __shfl_xor_sync(0xffffffffu, sum2, 2);
        float inv1 = 1.0f / sum1, inv2 = 1.0f / sum2;

        // P -> smem (C-layout to A-layout), warp-private rows
#pragma unroll
        for (int ni = 0; ni < 13; ni++) {
            int c0 = ni * 8 + tg * 2;
            *reinterpret_cast<float2*>(&p_s[r1 * 108 + c0]) =
                make_float2(tf32r(s[ni][0]), tf32r(s[ni][1]));
            *reinterpret_cast<float2*>(&p_s[r2 * 108 + c0]) =
                make_float2(tf32r(s[ni][2]), tf32r(s[ni][3]));
        }
        __syncwarp();

        // O = P @ V : 4 n8 tiles over 32 dims, 13 k-steps
        float o[4][4];
#pragma unroll
        for (int ni = 0; ni < 4; ni++) o[ni][0] = o[ni][1] = o[ni][2] = o[ni][3] = 0.f;
#pragma unroll
        for (int kt = 0; kt < 13; kt++) {
            float a0 = p_s[r1 * 108 + kt * 8 + tg],     a1 = p_s[r2 * 108 + kt * 8 + tg];
            float a2 = p_s[r1 * 108 + kt * 8 + tg + 4], a3 = p_s[r2 * 108 + kt * 8 + tg + 4];
#pragma unroll
            for (int ni = 0; ni < 4; ni++) {
                float b0 = v_s[(kt * 8 + tg) * 40 + ni * 8 + g];
                float b1 = v_s[(kt * 8 + tg + 4) * 40 + ni * 8 + g];
                mma8(o[ni], a0, a1, a2, a3, b0, b1);
            }
        }
        // store normalized O to g_o[b][n][h*32+d]
        float* gob = g_o + (size_t)b * NTOK * DIM + h * 32;
#pragma unroll
        for (int ni = 0; ni < 4; ni++) {
            int d = ni * 8 + tg * 2;
            if (r1 < NTOK)
                *reinterpret_cast<float2*>(&gob[r1 * DIM + d]) =
                    make_float2(o[ni][0] * inv1, o[ni][1] * inv1);
            if (r2 < NTOK)
                *reinterpret_cast<float2*>(&gob[r2 * DIM + d]) =
                    make_float2(o[ni][2] * inv2, o[ni][3] * inv2);
        }
    }
}

// ---------------- K3: output projection ----------------
__global__ void __launch_bounds__(256) k_proj(const float* __restrict__ w,
                                              const float* __restrict__ bias,
                                              float* __restrict__ out) {
    __shared__ float As[128][36];
    __shared__ float Bs[128][36];
    const int m0 = blockIdx.x * 128;
    const int tid = threadIdx.x, lane = tid & 31, warp = tid >> 5;
    const int g = lane >> 2, tg = lane & 3;
    const int wm = warp >> 2, wn = warp & 3;
    Frag64x32 F;
    gemm_tile(g_o, w, m0, 0, F, As, Bs);
#pragma unroll
    for (int ni = 0; ni < 4; ni++) {
        int col = wn * 32 + ni * 8 + tg * 2;
        float b0 = bias[col], b1 = bias[col + 1];
#pragma unroll
        for (int mi = 0; mi < 4; mi++) {
            int m = m0 + wm * 64 + mi * 16 + g;
            *reinterpret_cast<float2*>(&out[(size_t)m * 128 + col]) =
                make_float2(F.c[mi][ni][0] + b0, F.c[mi][ni][1] + b1);
            *reinterpret_cast<float2*>(&out[(size_t)(m + 8) * 128 + col]) =
                make_float2(F.c[mi][ni][2] + b0, F.c[mi][ni][3] + b1);
        }
    }
}

extern "C" void kernel_launch(void* const* d_in, const int* in_sizes, int n_in,
                              void* d_out, int out_size) {
    const float* x      = (const float*)d_in[0];
    const float* mask   = (const float*)d_in[1];
    const float* rpb    = (const float*)d_in[2];
    const float* qkv_w  = (const float*)d_in[3];
    const float* qkv_b  = (const float*)d_in[4];
    const float* proj_w = (const float*)d_in[5];
    const float* proj_b = (const float*)d_in[6];
    const int*   relidx = (const int*)d_in[7];
    float* out = (float*)d_out;

    cudaFuncSetAttribute(k_attn, cudaFuncAttributeMaxDynamicSharedMemorySize,
                         ATTN_SMEM_BYTES);

    k_comb<<<NW * HEADS, 256>>>(mask, rpb, relidx);
    k_qkv<<<dim3(BATCH * NTOK / 128, 3), 256>>>(x, qkv_w, qkv_b);
    k_attn<<<dim3(8, HEADS, NW), 256, ATTN_SMEM_BYTES>>>();
    k_proj<<<dim3(BATCH * NTOK / 128, 1), 256>>>(proj_w, proj_b, out);
}

// round 3
// speedup vs baseline: 1.4900x; 1.4900x over previous
#include <cuda_runtime.h>
#include <cstdint>
#include <cstddef>

#define NTOK   98
#define CSTR   108          // comb row stride (bank-conflict-free: 108 mod 32 = 12)
#define HEADS  4
#define DIM    128
#define BATCH  4096
#define NW     64
#define SCALE  0.17677669529663687f

__device__ float g_q[(size_t)BATCH * HEADS * NTOK * 32];
__device__ float g_k[(size_t)BATCH * HEADS * NTOK * 32];
__device__ float g_v[(size_t)BATCH * HEADS * NTOK * 32];
__device__ float g_o[(size_t)BATCH * NTOK * DIM];
__device__ float g_comb[(size_t)NW * HEADS * NTOK * CSTR];

__device__ __forceinline__ float ex2f(float x) {
    float y;
    asm("ex2.approx.f32 %0, %1;" : "=f"(y) : "f"(x));
    return y;
}
__device__ __forceinline__ void mma8(float c[4], float a0, float a1, float a2, float a3,
                                     float b0, float b1) {
    asm volatile(
        "mma.sync.aligned.m16n8k8.row.col.f32.tf32.tf32.f32 "
        "{%0,%1,%2,%3},{%4,%5,%6,%7},{%8,%9},{%0,%1,%2,%3};\n"
        : "+f"(c[0]), "+f"(c[1]), "+f"(c[2]), "+f"(c[3])
        : "r"(__float_as_uint(a0)), "r"(__float_as_uint(a1)),
          "r"(__float_as_uint(a2)), "r"(__float_as_uint(a3)),
          "r"(__float_as_uint(b0)), "r"(__float_as_uint(b1)));
}

// ---------------- K0: comb = mask + gathered bias, padded ----------------
__global__ void k_comb(const float* __restrict__ mask,
                       const float* __restrict__ rpb,
                       const int* __restrict__ relidx) {
    const int w = blockIdx.x >> 2, h = blockIdx.x & 3;
    float* dst = g_comb + (size_t)(w * HEADS + h) * NTOK * CSTR;
    const float* msk = mask + (size_t)w * NTOK * NTOK;
    for (int idx = threadIdx.x; idx < NTOK * CSTR; idx += blockDim.x) {
        int i = idx / CSTR, j = idx - i * CSTR;
        float v = -10000.0f;
        if (j < NTOK) v = msk[i * NTOK + j] + rpb[relidx[i * NTOK + j] * HEADS + h];
        dst[idx] = v;
    }
}

// ---------------- K1: QKV GEMM, x-tile resident, 3 n-tiles per block ----------------
#define QKV_SMEM_BYTES ((128 * 132 + 128 * 36) * 4)

__global__ void __launch_bounds__(256, 2) k_qkv(const float* __restrict__ x,
                                                const float* __restrict__ w,
                                                const float* __restrict__ bias) {
    extern __shared__ float smq[];
    float (*As)[132] = reinterpret_cast<float(*)[132]>(smq);
    float (*Bs)[36]  = reinterpret_cast<float(*)[36]>(smq + 128 * 132);
    const int m0 = blockIdx.x * 128;
    const int tid = threadIdx.x, lane = tid & 31, warp = tid >> 5;
    const int g = lane >> 2, tg = lane & 3;
    const int wm = warp >> 2, wn = warp & 3;

    {   // load full 128x128 x tile once
        const int c = (tid & 31) * 4, rb = tid >> 5;
#pragma unroll
        for (int rr = 0; rr < 16; rr++) {
            int r = rb + rr * 8;
            *reinterpret_cast<float4*>(&As[r][c]) =
                *reinterpret_cast<const float4*>(&x[(size_t)(m0 + r) * 128 + c]);
        }
    }

    const int fi = (tid & 7) * 4, r0 = tid >> 3;
    for (int n0 = 0; n0 < 384; n0 += 128) {
        float c4[4][4][4];
#pragma unroll
        for (int i = 0; i < 4; i++)
#pragma unroll
            for (int j = 0; j < 4; j++)
#pragma unroll
                for (int q = 0; q < 4; q++) c4[i][j][q] = 0.f;

        for (int kk = 0; kk < 128; kk += 32) {
#pragma unroll
            for (int rr = 0; rr < 4; rr++) {
                int r = r0 + rr * 32;
                *reinterpret_cast<float4*>(&Bs[r][fi]) =
                    *reinterpret_cast<const float4*>(&w[(size_t)(n0 + r) * 128 + kk + fi]);
            }
            __syncthreads();
#pragma unroll
            for (int ks = 0; ks < 32; ks += 8) {
                float a[4][4], bb[4][2];
#pragma unroll
                for (int mi = 0; mi < 4; mi++) {
                    int rr = wm * 64 + mi * 16 + g;
                    a[mi][0] = As[rr][kk + ks + tg];     a[mi][1] = As[rr + 8][kk + ks + tg];
                    a[mi][2] = As[rr][kk + ks + tg + 4]; a[mi][3] = As[rr + 8][kk + ks + tg + 4];
                }
#pragma unroll
                for (int ni = 0; ni < 4; ni++) {
                    int cc = wn * 32 + ni * 8 + g;
                    bb[ni][0] = Bs[cc][ks + tg]; bb[ni][1] = Bs[cc][ks + tg + 4];
                }
#pragma unroll
                for (int mi = 0; mi < 4; mi++)
#pragma unroll
                    for (int ni = 0; ni < 4; ni++)
                        mma8(c4[mi][ni], a[mi][0], a[mi][1], a[mi][2], a[mi][3],
                             bb[ni][0], bb[ni][1]);
            }
            __syncthreads();
        }
        // epilogue: + bias, scatter
#pragma unroll
        for (int ni = 0; ni < 4; ni++) {
            int col = n0 + wn * 32 + ni * 8 + tg * 2;
            float b0 = bias[col], b1 = bias[col + 1];
            int sel = col >> 7, o = col & 127, h = o >> 5, d = o & 31;
            float* base = (sel == 0) ? g_q : ((sel == 1) ? g_k : g_v);
#pragma unroll
            for (int mi = 0; mi < 4; mi++) {
                int m = m0 + wm * 64 + mi * 16 + g;
                int b = m / NTOK, n = m - b * NTOK;
                *reinterpret_cast<float2*>(&base[(((size_t)b * HEADS + h) * NTOK + n) * 32 + d]) =
                    make_float2(c4[mi][ni][0] + b0, c4[mi][ni][1] + b1);
                int m2 = m + 8, b2 = m2 / NTOK, n2 = m2 - b2 * NTOK;
                *reinterpret_cast<float2*>(&base[(((size_t)b2 * HEADS + h) * NTOK + n2) * 32 + d]) =
                    make_float2(c4[mi][ni][2] + b0, c4[mi][ni][3] + b1);
            }
        }
    }
}

// ---------------- K2: fused attention, smem-lean, shfl P-transpose ----------------
#define SM_KS (NTOK * CSTR)            // comb: 98*108
#define SM_VS (SM_KS + 104 * 36)       // k_s
#define ATTN_SMEM_BYTES ((SM_VS + 104 * 40) * 4)

__global__ void __launch_bounds__(256, 2) k_attn() {
    extern __shared__ float sm[];
    float* comb_s = sm;                // [98][108]
    float* k_s = sm + SM_KS;           // [104][36], rows>=98 zero
    float* v_s = sm + SM_VS;           // [104][40], rows>=98 zero

    const int t = blockIdx.x, h = blockIdx.y, w = blockIdx.z;
    const int tid = threadIdx.x, lane = tid & 31, warp = tid >> 5;
    const int g = lane >> 2, tg = lane & 3;
    const int r1 = warp * 16 + g, r2 = r1 + 8;
    const int cr1 = min(r1, NTOK - 1), cr2 = min(r2, NTOK - 1);
    const unsigned FULL = 0xffffffffu;
    const int o1 = (lane & ~3) + (tg >> 1), o2 = o1 + 2;
    const bool el = (tg & 1);
    const float L2E = 1.4426950408889634f;

    {
        const float* cg = g_comb + (size_t)(w * HEADS + h) * NTOK * CSTR;
        for (int i = tid; i < NTOK * CSTR; i += 256) comb_s[i] = cg[i];
    }

    for (int jj = 0; jj < 8; jj++) {
        const int b = (t * 8 + jj) * NW + w;
        const size_t off = ((size_t)b * HEADS + h) * NTOK * 32;
        const float* gq = g_q + off;
        const float* gk = g_k + off;
        const float* gv = g_v + off;
        __syncthreads();
        for (int i = tid; i < 104 * 8; i += 256) {
            int r = i >> 3, f = (i & 7) * 4;
            float4 kv = make_float4(0.f, 0.f, 0.f, 0.f), vv = kv;
            if (r < NTOK) {
                kv = *reinterpret_cast<const float4*>(&gk[r * 32 + f]);
                vv = *reinterpret_cast<const float4*>(&gv[r * 32 + f]);
            }
            *reinterpret_cast<float4*>(&k_s[r * 36 + f]) = kv;
            *reinterpret_cast<float4*>(&v_s[r * 40 + f]) = vv;
        }
        // q fragments straight from global (warp-private rows)
        float qa[4][4];
#pragma unroll
        for (int ks4 = 0; ks4 < 4; ks4++) {
            qa[ks4][0] = qa[ks4][1] = qa[ks4][2] = qa[ks4][3] = 0.f;
            if (r1 < NTOK) {
                qa[ks4][0] = gq[r1 * 32 + ks4 * 8 + tg] * SCALE;
                qa[ks4][2] = gq[r1 * 32 + ks4 * 8 + tg + 4] * SCALE;
            }
            if (r2 < NTOK) {
                qa[ks4][1] = gq[r2 * 32 + ks4 * 8 + tg] * SCALE;
                qa[ks4][3] = gq[r2 * 32 + ks4 * 8 + tg + 4] * SCALE;
            }
        }
        __syncthreads();

        // S = q @ k^T
        float s[13][4];
#pragma unroll
        for (int ni = 0; ni < 13; ni++)
            s[ni][0] = s[ni][1] = s[ni][2] = s[ni][3] = 0.f;
#pragma unroll
        for (int ks4 = 0; ks4 < 4; ks4++) {
#pragma unroll
            for (int ni = 0; ni < 13; ni++) {
                float b0 = k_s[(ni * 8 + g) * 36 + ks4 * 8 + tg];
                float b1 = k_s[(ni * 8 + g) * 36 + ks4 * 8 + tg + 4];
                mma8(s[ni], qa[ks4][0], qa[ks4][1], qa[ks4][2], qa[ks4][3], b0, b1);
            }
        }
        // bias + quad softmax
        float m1 = -1e30f, m2 = -1e30f;
#pragma unroll
        for (int ni = 0; ni < 13; ni++) {
            int c0 = ni * 8 + tg * 2;
            s[ni][0] += comb_s[cr1 * CSTR + c0];
            s[ni][1] += comb_s[cr1 * CSTR + c0 + 1];
            s[ni][2] += comb_s[cr2 * CSTR + c0];
            s[ni][3] += comb_s[cr2 * CSTR + c0 + 1];
            m1 = fmaxf(m1, fmaxf(s[ni][0], s[ni][1]));
            m2 = fmaxf(m2, fmaxf(s[ni][2], s[ni][3]));
        }
        m1 = fmaxf(m1, __shfl_xor_sync(FULL, m1, 1));
        m1 = fmaxf(m1, __shfl_xor_sync(FULL, m1, 2));
        m2 = fmaxf(m2, __shfl_xor_sync(FULL, m2, 1));
        m2 = fmaxf(m2, __shfl_xor_sync(FULL, m2, 2));
        float sum1 = 0.f, sum2 = 0.f;
#pragma unroll
        for (int ni = 0; ni < 13; ni++) {
            s[ni][0] = ex2f((s[ni][0] - m1) * L2E);
            s[ni][1] = ex2f((s[ni][1] - m1) * L2E);
            s[ni][2] = ex2f((s[ni][2] - m2) * L2E);
            s[ni][3] = ex2f((s[ni][3] - m2) * L2E);
            sum1 += s[ni][0] + s[ni][1];
            sum2 += s[ni][2] + s[ni][3];
        }
        sum1 += __shfl_xor_sync(FULL, sum1, 1);
        sum1 += __shfl_xor_sync(FULL, sum1, 2);
        sum2 += __shfl_xor_sync(FULL, sum2, 1);
        sum2 += __shfl_xor_sync(FULL, sum2, 2);
        float inv1 = 1.0f / sum1, inv2 = 1.0f / sum2;

        // O = P @ V, P transposed C->A layout via intra-quad shfl
        float o[4][4];
#pragma unroll
        for (int ni = 0; ni < 4; ni++) o[ni][0] = o[ni][1] = o[ni][2] = o[ni][3] = 0.f;
#pragma unroll
        for (int kt = 0; kt < 13; kt++) {
            float v00 = __shfl_sync(FULL, s[kt][0], o1);
            float v01 = __shfl_sync(FULL, s[kt][1], o1);
            float v02 = __shfl_sync(FULL, s[kt][2], o1);
            float v03 = __shfl_sync(FULL, s[kt][3], o1);
            float a0 = el ? v01 : v00;   // P[r1][kt*8+tg]
            float a1 = el ? v03 : v02;   // P[r2][kt*8+tg]
            float w00 = __shfl_sync(FULL, s[kt][0], o2);
            float w01 = __shfl_sync(FULL, s[kt][1], o2);
            float w02 = __shfl_sync(FULL, s[kt][2], o2);
            float w03 = __shfl_sync(FULL, s[kt][3], o2);
            float a2 = el ? w01 : w00;   // P[r1][kt*8+tg+4]
            float a3 = el ? w03 : w02;   // P[r2][kt*8+tg+4]
#pragma unroll
            for (int ni = 0; ni < 4; ni++) {
                float b0 = v_s[(kt * 8 + tg) * 40 + ni * 8 + g];
                float b1 = v_s[(kt * 8 + tg + 4) * 40 + ni * 8 + g];
                mma8(o[ni], a0, a1, a2, a3, b0, b1);
            }
        }
        // store normalized O
        float* gob = g_o + (size_t)b * NTOK * DIM + h * 32;
#pragma unroll
        for (int ni = 0; ni < 4; ni++) {
            int d = ni * 8 + tg * 2;
            if (r1 < NTOK)
                *reinterpret_cast<float2*>(&gob[r1 * DIM + d]) =
                    make_float2(o[ni][0] * inv1, o[ni][1] * inv1);
            if (r2 < NTOK)
                *reinterpret_cast<float2*>(&gob[r2 * DIM + d]) =
                    make_float2(o[ni][2] * inv2, o[ni][3] * inv2);
        }
    }
}

// ---------------- K3: output projection ----------------
__global__ void __launch_bounds__(256) k_proj(const float* __restrict__ w,
                                              const float* __restrict__ bias,
                                              float* __restrict__ out) {
    __shared__ float As[128][36];
    __shared__ float Bs[128][36];
    const int m0 = blockIdx.x * 128;
    const int tid = threadIdx.x, lane = tid & 31, warp = tid >> 5;
    const int g = lane >> 2, tg = lane & 3;
    const int wm = warp >> 2, wn = warp & 3;
    const int fi = (tid & 7) * 4, r0 = tid >> 3;

    float c4[4][4][4];
#pragma unroll
    for (int i = 0; i < 4; i++)
#pragma unroll
        for (int j = 0; j < 4; j++)
#pragma unroll
            for (int q = 0; q < 4; q++) c4[i][j][q] = 0.f;

    for (int kk = 0; kk < 128; kk += 32) {
#pragma unroll
        for (int rr = 0; rr < 4; rr++) {
            int r = r0 + rr * 32;
            *reinterpret_cast<float4*>(&As[r][fi]) =
                *reinterpret_cast<const float4*>(&g_o[(size_t)(m0 + r) * 128 + kk + fi]);
            *reinterpret_cast<float4*>(&Bs[r][fi]) =
                *reinterpret_cast<const float4*>(&w[(size_t)r * 128 + kk + fi]);
        }
        __syncthreads();
#pragma unroll
        for (int ks = 0; ks < 32; ks += 8) {
            float a[4][4], bb[4][2];
#pragma unroll
            for (int mi = 0; mi < 4; mi++) {
                int rr = wm * 64 + mi * 16 + g;
                a[mi][0] = As[rr][ks + tg];     a[mi][1] = As[rr + 8][ks + tg];
                a[mi][2] = As[rr][ks + tg + 4]; a[mi][3] = As[rr + 8][ks + tg + 4];
            }
#pragma unroll
            for (int ni = 0; ni < 4; ni++) {
                int cc = wn * 32 + ni * 8 + g;
                bb[ni][0] = Bs[cc][ks + tg]; bb[ni][1] = Bs[cc][ks + tg + 4];
            }
#pragma unroll
            for (int mi = 0; mi < 4; mi++)
#pragma unroll
                for (int ni = 0; ni < 4; ni++)
                    mma8(c4[mi][ni], a[mi][0], a[mi][1], a[mi][2], a[mi][3],
                         bb[ni][0], bb[ni][1]);
        }
        __syncthreads();
    }
#pragma unroll
    for (int ni = 0; ni < 4; ni++) {
        int col = wn * 32 + ni * 8 + tg * 2;
        float b0 = bias[col], b1 = bias[col + 1];
#pragma unroll
        for (int mi = 0; mi < 4; mi++) {
            int m = m0 + wm * 64 + mi * 16 + g;
            *reinterpret_cast<float2*>(&out[(size_t)m * 128 + col]) =
                make_float2(c4[mi][ni][0] + b0, c4[mi][ni][1] + b1);
            *reinterpret_cast<float2*>(&out[(size_t)(m + 8) * 128 + col]) =
                make_float2(c4[mi][ni][2] + b0, c4[mi][ni][3] + b1);
        }
    }
}

extern "C" void kernel_launch(void* const* d_in, const int* in_sizes, int n_in,
                              void* d_out, int out_size) {
    const float* x      = (const float*)d_in[0];
    const float* mask   = (const float*)d_in[1];
    const float* rpb    = (const float*)d_in[2];
    const float* qkv_w  = (const float*)d_in[3];
    const float* qkv_b  = (const float*)d_in[4];
    const float* proj_w = (const float*)d_in[5];
    const float* proj_b = (const float*)d_in[6];
    const int*   relidx = (const int*)d_in[7];
    float* out = (float*)d_out;

    cudaFuncSetAttribute(k_qkv, cudaFuncAttributeMaxDynamicSharedMemorySize, QKV_SMEM_BYTES);
    cudaFuncSetAttribute(k_attn, cudaFuncAttributeMaxDynamicSharedMemorySize, ATTN_SMEM_BYTES);

    k_comb<<<NW * HEADS, 256>>>(mask, rpb, relidx);
    k_qkv<<<BATCH * NTOK / 128, 256, QKV_SMEM_BYTES>>>(x, qkv_w, qkv_b);
    k_attn<<<dim3(8, HEADS, NW), 256, ATTN_SMEM_BYTES>>>();
    k_proj<<<BATCH * NTOK / 128, 256>>>(proj_w, proj_b, out);
}

// round 4
// speedup vs baseline: 1.6064x; 1.0781x over previous
#include <cuda_runtime.h>
#include <cstdint>
#include <cstddef>

#define NTOK   98
#define CSTR   108
#define HEADS  4
#define DIM    128
#define BATCH  4096
#define NW     64
#define SCALE  0.17677669529663687f

__device__ float g_q[(size_t)BATCH * HEADS * NTOK * 32];
__device__ float g_k[(size_t)BATCH * HEADS * NTOK * 32];
__device__ float g_v[(size_t)BATCH * HEADS * NTOK * 32];
__device__ float g_o[(size_t)BATCH * NTOK * DIM];
__device__ float g_comb[(size_t)NW * HEADS * NTOK * CSTR];

__device__ __forceinline__ float tf32r(float x) {
    unsigned u;
    asm("cvt.rna.tf32.f32 %0, %1;" : "=r"(u) : "f"(x));
    return __uint_as_float(u);
}
__device__ __forceinline__ float ex2f(float x) {
    float y;
    asm("ex2.approx.f32 %0, %1;" : "=f"(y) : "f"(x));
    return y;
}
__device__ __forceinline__ void mma8(float c[4], float a0, float a1, float a2, float a3,
                                     float b0, float b1) {
    asm volatile(
        "mma.sync.aligned.m16n8k8.row.col.f32.tf32.tf32.f32 "
        "{%0,%1,%2,%3},{%4,%5,%6,%7},{%8,%9},{%0,%1,%2,%3};\n"
        : "+f"(c[0]), "+f"(c[1]), "+f"(c[2]), "+f"(c[3])
        : "r"(__float_as_uint(a0)), "r"(__float_as_uint(a1)),
          "r"(__float_as_uint(a2)), "r"(__float_as_uint(a3)),
          "r"(__float_as_uint(b0)), "r"(__float_as_uint(b1)));
}
__device__ __forceinline__ void cp16(void* sptr, const void* gptr) {
    unsigned s = (unsigned)__cvta_generic_to_shared(sptr);
    asm volatile("cp.async.cg.shared.global [%0], [%1], 16;\n" :: "r"(s), "l"(gptr));
}
#define CP_COMMIT() asm volatile("cp.async.commit_group;\n" ::: "memory")
#define CP_WAIT0()  asm volatile("cp.async.wait_group 0;\n" ::: "memory")

// ---------------- K0: comb = mask + gathered bias, padded ----------------
__global__ void k_comb(const float* __restrict__ mask,
                       const float* __restrict__ rpb,
                       const int* __restrict__ relidx) {
    const int w = blockIdx.x >> 2, h = blockIdx.x & 3;
    float* dst = g_comb + (size_t)(w * HEADS + h) * NTOK * CSTR;
    const float* msk = mask + (size_t)w * NTOK * NTOK;
    for (int idx = threadIdx.x; idx < NTOK * CSTR; idx += blockDim.x) {
        int i = idx / CSTR, j = idx - i * CSTR;
        float v = -10000.0f;
        if (j < NTOK) v = msk[i * NTOK + j] + rpb[relidx[i * NTOK + j] * HEADS + h];
        dst[idx] = v;
    }
}

// ---------------- K1: QKV GEMM, x-tile resident, 3 n-tiles per block ----------------
#define QKV_SMEM_BYTES ((128 * 132 + 128 * 36) * 4)

__global__ void __launch_bounds__(256, 2) k_qkv(const float* __restrict__ x,
                                                const float* __restrict__ w,
                                                const float* __restrict__ bias) {
    extern __shared__ float smq[];
    float (*As)[132] = reinterpret_cast<float(*)[132]>(smq);
    float (*Bs)[36]  = reinterpret_cast<float(*)[36]>(smq + 128 * 132);
    const int m0 = blockIdx.x * 128;
    const int tid = threadIdx.x, lane = tid & 31, warp = tid >> 5;
    const int g = lane >> 2, tg = lane & 3;
    const int wm = warp >> 2, wn = warp & 3;

    {   // load full 128x128 x tile once (rna-rounded)
        const int c = (tid & 31) * 4, rb = tid >> 5;
#pragma unroll
        for (int rr = 0; rr < 16; rr++) {
            int r = rb + rr * 8;
            float4 v4 = *reinterpret_cast<const float4*>(&x[(size_t)(m0 + r) * 128 + c]);
            *reinterpret_cast<float4*>(&As[r][c]) =
                make_float4(tf32r(v4.x), tf32r(v4.y), tf32r(v4.z), tf32r(v4.w));
        }
    }

    const int fi = (tid & 7) * 4, r0 = tid >> 3;
    for (int n0 = 0; n0 < 384; n0 += 128) {
        float c4[4][4][4];
#pragma unroll
        for (int i = 0; i < 4; i++)
#pragma unroll
            for (int j = 0; j < 4; j++)
#pragma unroll
                for (int q = 0; q < 4; q++) c4[i][j][q] = 0.f;

        for (int kk = 0; kk < 128; kk += 32) {
#pragma unroll
            for (int rr = 0; rr < 4; rr++) {
                int r = r0 + rr * 32;
                float4 vb = *reinterpret_cast<const float4*>(&w[(size_t)(n0 + r) * 128 + kk + fi]);
                *reinterpret_cast<float4*>(&Bs[r][fi]) =
                    make_float4(tf32r(vb.x), tf32r(vb.y), tf32r(vb.z), tf32r(vb.w));
            }
            __syncthreads();
#pragma unroll
            for (int ks = 0; ks < 32; ks += 8) {
                float a[4][4], bb[4][2];
#pragma unroll
                for (int mi = 0; mi < 4; mi++) {
                    int rr = wm * 64 + mi * 16 + g;
                    a[mi][0] = As[rr][kk + ks + tg];     a[mi][1] = As[rr + 8][kk + ks + tg];
                    a[mi][2] = As[rr][kk + ks + tg + 4]; a[mi][3] = As[rr + 8][kk + ks + tg + 4];
                }
#pragma unroll
                for (int ni = 0; ni < 4; ni++) {
                    int cc = wn * 32 + ni * 8 + g;
                    bb[ni][0] = Bs[cc][ks + tg]; bb[ni][1] = Bs[cc][ks + tg + 4];
                }
#pragma unroll
                for (int mi = 0; mi < 4; mi++)
#pragma unroll
                    for (int ni = 0; ni < 4; ni++)
                        mma8(c4[mi][ni], a[mi][0], a[mi][1], a[mi][2], a[mi][3],
                             bb[ni][0], bb[ni][1]);
            }
            __syncthreads();
        }
#pragma unroll
        for (int ni = 0; ni < 4; ni++) {
            int col = n0 + wn * 32 + ni * 8 + tg * 2;
            float b0 = bias[col], b1 = bias[col + 1];
            int sel = col >> 7, o = col & 127, h = o >> 5, d = o & 31;
            float* base = (sel == 0) ? g_q : ((sel == 1) ? g_k : g_v);
#pragma unroll
            for (int mi = 0; mi < 4; mi++) {
                int m = m0 + wm * 64 + mi * 16 + g;
                int b = m / NTOK, n = m - b * NTOK;
                *reinterpret_cast<float2*>(&base[(((size_t)b * HEADS + h) * NTOK + n) * 32 + d]) =
                    make_float2(c4[mi][ni][0] + b0, c4[mi][ni][1] + b1);
                int m2 = m + 8, b2 = m2 / NTOK, n2 = m2 - b2 * NTOK;
                *reinterpret_cast<float2*>(&base[(((size_t)b2 * HEADS + h) * NTOK + n2) * 32 + d]) =
                    make_float2(c4[mi][ni][2] + b0, c4[mi][ni][3] + b1);
            }
        }
    }
}

// ---------------- K2: fused attention, 7 warps, double-buffered k/v ----------------
#define KSTR 36
#define VSTR 40
#define KBUF (104 * KSTR)
#define VBUF (104 * VSTR)
#define SM_KS (NTOK * CSTR)
#define SM_VS (SM_KS + 2 * KBUF)
#define ATTN_SMEM_BYTES ((SM_VS + 2 * VBUF) * 4)
#define ATHREADS 224

__global__ void __launch_bounds__(ATHREADS, 2) k_attn() {
    extern __shared__ float sm[];
    float* comb_s = sm;                 // [98][108]
    float* k_sb = sm + SM_KS;           // [2][104][36]
    float* v_sb = sm + SM_VS;           // [2][104][40]

    const int t = blockIdx.x, h = blockIdx.y, w = blockIdx.z;
    const int tid = threadIdx.x, lane = tid & 31, warp = tid >> 5;
    const int g = lane >> 2, tg = lane & 3;
    const int r1 = warp * 16 + g, r2 = r1 + 8;
    const int cr1 = min(r1, NTOK - 1), cr2 = min(r2, NTOK - 1);
    const unsigned FULL = 0xffffffffu;
    const int o1 = (lane & ~3) + (tg >> 1), o2 = o1 + 2;
    const bool el = (tg & 1);
    const float L2E = 1.4426950408889634f;

    {
        const float* cg = g_comb + (size_t)(w * HEADS + h) * NTOK * CSTR;
        for (int i = tid; i < NTOK * CSTR; i += ATHREADS) comb_s[i] = cg[i];
    }
    // zero pad rows 98..103 (never touched by cp.async)
    for (int i = tid; i < 6 * KSTR; i += ATHREADS) {
        k_sb[98 * KSTR + i] = 0.f; k_sb[KBUF + 98 * KSTR + i] = 0.f;
    }
    for (int i = tid; i < 6 * VSTR; i += ATHREADS) {
        v_sb[98 * VSTR + i] = 0.f; v_sb[VBUF + 98 * VSTR + i] = 0.f;
    }

    auto prefetch = [&](int jj, int buf) {
        const int b = (t * 8 + jj) * NW + w;
        const size_t off = ((size_t)b * HEADS + h) * NTOK * 32;
        const float* gk = g_k + off;
        const float* gv = g_v + off;
        float* kd = k_sb + buf * KBUF;
        float* vd = v_sb + buf * VBUF;
#pragma unroll
        for (int ii = 0; ii < 7; ii++) {
            int i = tid + ii * ATHREADS;           // 0..1567
            int tsel = (i >= 784);
            int j = tsel ? i - 784 : i;
            int r = j >> 3, f = (j & 7) * 4;
            if (tsel) cp16(&vd[r * VSTR + f], &gv[r * 32 + f]);
            else      cp16(&kd[r * KSTR + f], &gk[r * 32 + f]);
        }
    };
    prefetch(0, 0);
    CP_COMMIT();

    for (int jj = 0; jj < 8; jj++) {
        const int cur = jj & 1;
        const int b = (t * 8 + jj) * NW + w;
        const float* gq = g_q + ((size_t)b * HEADS + h) * NTOK * 32;
        const float* kb = k_sb + cur * KBUF;
        const float* vb = v_sb + cur * VBUF;

        // q fragments from global (independent of smem buffers) — overlap the wait
        float qa[4][4];
#pragma unroll
        for (int ks4 = 0; ks4 < 4; ks4++) {
            qa[ks4][0] = qa[ks4][1] = qa[ks4][2] = qa[ks4][3] = 0.f;
            if (r1 < NTOK) {
                qa[ks4][0] = tf32r(gq[r1 * 32 + ks4 * 8 + tg] * SCALE);
                qa[ks4][2] = tf32r(gq[r1 * 32 + ks4 * 8 + tg + 4] * SCALE);
            }
            if (r2 < NTOK) {
                qa[ks4][1] = tf32r(gq[r2 * 32 + ks4 * 8 + tg] * SCALE);
                qa[ks4][3] = tf32r(gq[r2 * 32 + ks4 * 8 + tg + 4] * SCALE);
            }
        }
        CP_WAIT0();
        __syncthreads();           // buffers ready + previous compute done
        if (jj < 7) {              // prefetch next into the other buffer, overlaps compute
            prefetch(jj + 1, cur ^ 1);
            CP_COMMIT();
        }

        // S = q @ k^T
        float s[13][4];
#pragma unroll
        for (int ni = 0; ni < 13; ni++)
            s[ni][0] = s[ni][1] = s[ni][2] = s[ni][3] = 0.f;
#pragma unroll
        for (int ks4 = 0; ks4 < 4; ks4++) {
#pragma unroll
            for (int ni = 0; ni < 13; ni++) {
                float b0 = kb[(ni * 8 + g) * KSTR + ks4 * 8 + tg];
                float b1 = kb[(ni * 8 + g) * KSTR + ks4 * 8 + tg + 4];
                mma8(s[ni], qa[ks4][0], qa[ks4][1], qa[ks4][2], qa[ks4][3], b0, b1);
            }
        }
        // bias + quad softmax
        float m1 = -1e30f, m2 = -1e30f;
#pragma unroll
        for (int ni = 0; ni < 13; ni++) {
            int c0 = ni * 8 + tg * 2;
            s[ni][0] += comb_s[cr1 * CSTR + c0];
            s[ni][1] += comb_s[cr1 * CSTR + c0 + 1];
            s[ni][2] += comb_s[cr2 * CSTR + c0];
            s[ni][3] += comb_s[cr2 * CSTR + c0 + 1];
            m1 = fmaxf(m1, fmaxf(s[ni][0], s[ni][1]));
            m2 = fmaxf(m2, fmaxf(s[ni][2], s[ni][3]));
        }
        m1 = fmaxf(m1, __shfl_xor_sync(FULL, m1, 1));
        m1 = fmaxf(m1, __shfl_xor_sync(FULL, m1, 2));
        m2 = fmaxf(m2, __shfl_xor_sync(FULL, m2, 1));
        m2 = fmaxf(m2, __shfl_xor_sync(FULL, m2, 2));
        float sum1 = 0.f, sum2 = 0.f;
#pragma unroll
        for (int ni = 0; ni < 13; ni++) {
            s[ni][0] = tf32r(ex2f((s[ni][0] - m1) * L2E));
            s[ni][1] = tf32r(ex2f((s[ni][1] - m1) * L2E));
            s[ni][2] = tf32r(ex2f((s[ni][2] - m2) * L2E));
            s[ni][3] = tf32r(ex2f((s[ni][3] - m2) * L2E));
            sum1 += s[ni][0] + s[ni][1];
            sum2 += s[ni][2] + s[ni][3];
        }
        sum1 += __shfl_xor_sync(FULL, sum1, 1);
        sum1 += __shfl_xor_sync(FULL, sum1, 2);
        sum2 += __shfl_xor_sync(FULL, sum2, 1);
        sum2 += __shfl_xor_sync(FULL, sum2, 2);
        float inv1 = 1.0f / sum1, inv2 = 1.0f / sum2;

        // O = P @ V, P transposed C->A layout via intra-quad shfl
        float o[4][4];
#pragma unroll
        for (int ni = 0; ni < 4; ni++) o[ni][0] = o[ni][1] = o[ni][2] = o[ni][3] = 0.f;
#pragma unroll
        for (int kt = 0; kt < 13; kt++) {
            float v00 = __shfl_sync(FULL, s[kt][0], o1);
            float v01 = __shfl_sync(FULL, s[kt][1], o1);
            float v02 = __shfl_sync(FULL, s[kt][2], o1);
            float v03 = __shfl_sync(FULL, s[kt][3], o1);
            float a0 = el ? v01 : v00;
            float a1 = el ? v03 : v02;
            float w00 = __shfl_sync(FULL, s[kt][0], o2);
            float w01 = __shfl_sync(FULL, s[kt][1], o2);
            float w02 = __shfl_sync(FULL, s[kt][2], o2);
            float w03 = __shfl_sync(FULL, s[kt][3], o2);
            float a2 = el ? w01 : w00;
            float a3 = el ? w03 : w02;
#pragma unroll
            for (int ni = 0; ni < 4; ni++) {
                float b0 = vb[(kt * 8 + tg) * VSTR + ni * 8 + g];
                float b1 = vb[(kt * 8 + tg + 4) * VSTR + ni * 8 + g];
                mma8(o[ni], a0, a1, a2, a3, b0, b1);
            }
        }
        float* gob = g_o + (size_t)b * NTOK * DIM + h * 32;
#pragma unroll
        for (int ni = 0; ni < 4; ni++) {
            int d = ni * 8 + tg * 2;
            if (r1 < NTOK)
                *reinterpret_cast<float2*>(&gob[r1 * DIM + d]) =
                    make_float2(o[ni][0] * inv1, o[ni][1] * inv1);
            if (r2 < NTOK)
                *reinterpret_cast<float2*>(&gob[r2 * DIM + d]) =
                    make_float2(o[ni][2] * inv2, o[ni][3] * inv2);
        }
    }
}

// ---------------- K3: output projection ----------------
__global__ void __launch_bounds__(256) k_proj(const float* __restrict__ w,
                                              const float* __restrict__ bias,
                                              float* __restrict__ out) {
    __shared__ float As[128][36];
    __shared__ float Bs[128][36];
    const int m0 = blockIdx.x * 128;
    const int tid = threadIdx.x, lane = tid & 31, warp = tid >> 5;
    const int g = lane >> 2, tg = lane & 3;
    const int wm = warp >> 2, wn = warp & 3;
    const int fi = (tid & 7) * 4, r0 = tid >> 3;

    float c4[4][4][4];
#pragma unroll
    for (int i = 0; i < 4; i++)
#pragma unroll
        for (int j = 0; j < 4; j++)
#pragma unroll
            for (int q = 0; q < 4; q++) c4[i][j][q] = 0.f;

    for (int kk = 0; kk < 128; kk += 32) {
#pragma unroll
        for (int rr = 0; rr < 4; rr++) {
            int r = r0 + rr * 32;
            float4 va = *reinterpret_cast<const float4*>(&g_o[(size_t)(m0 + r) * 128 + kk + fi]);
            float4 vb = *reinterpret_cast<const float4*>(&w[(size_t)r * 128 + kk + fi]);
            *reinterpret_cast<float4*>(&As[r][fi]) =
                make_float4(tf32r(va.x), tf32r(va.y), tf32r(va.z), tf32r(va.w));
            *reinterpret_cast<float4*>(&Bs[r][fi]) =
                make_float4(tf32r(vb.x), tf32r(vb.y), tf32r(vb.z), tf32r(vb.w));
        }
        __syncthreads();
#pragma unroll
        for (int ks = 0; ks < 32; ks += 8) {
            float a[4][4], bb[4][2];
#pragma unroll
            for (int mi = 0; mi < 4; mi++) {
                int rr = wm * 64 + mi * 16 + g;
                a[mi][0] = As[rr][ks + tg];     a[mi][1] = As[rr + 8][ks + tg];
                a[mi][2] = As[rr][ks + tg + 4]; a[mi][3] = As[rr + 8][ks + tg + 4];
            }
#pragma unroll
            for (int ni = 0; ni < 4; ni++) {
                int cc = wn * 32 + ni * 8 + g;
                bb[ni][0] = Bs[cc][ks + tg]; bb[ni][1] = Bs[cc][ks + tg + 4];
            }
#pragma unroll
            for (int mi = 0; mi < 4; mi++)
#pragma unroll
                for (int ni = 0; ni < 4; ni++)
                    mma8(c4[mi][ni], a[mi][0], a[mi][1], a[mi][2], a[mi][3],
                         bb[ni][0], bb[ni][1]);
        }
        __syncthreads();
    }
#pragma unroll
    for (int ni = 0; ni < 4; ni++) {
        int col = wn * 32 + ni * 8 + tg * 2;
        float b0 = bias[col], b1 = bias[col + 1];
#pragma unroll
        for (int mi = 0; mi < 4; mi++) {
            int m = m0 + wm * 64 + mi * 16 + g;
            *reinterpret_cast<float2*>(&out[(size_t)m * 128 + col]) =
                make_float2(c4[mi][ni][0] + b0, c4[mi][ni][1] + b1);
            *reinterpret_cast<float2*>(&out[(size_t)(m + 8) * 128 + col]) =
                make_float2(c4[mi][ni][2] + b0, c4[mi][ni][3] + b1);
        }
    }
}

extern "C" void kernel_launch(void* const* d_in, const int* in_sizes, int n_in,
                              void* d_out, int out_size) {
    const float* x      = (const float*)d_in[0];
    const float* mask   = (const float*)d_in[1];
    const float* rpb    = (const float*)d_in[2];
    const float* qkv_w  = (const float*)d_in[3];
    const float* qkv_b  = (const float*)d_in[4];
    const float* proj_w = (const float*)d_in[5];
    const float* proj_b = (const float*)d_in[6];
    const int*   relidx = (const int*)d_in[7];
    float* out = (float*)d_out;

    cudaFuncSetAttribute(k_qkv, cudaFuncAttributeMaxDynamicSharedMemorySize, QKV_SMEM_BYTES);
    cudaFuncSetAttribute(k_attn, cudaFuncAttributeMaxDynamicSharedMemorySize, ATTN_SMEM_BYTES);

    k_comb<<<NW * HEADS, 256>>>(mask, rpb, relidx);
    k_qkv<<<BATCH * NTOK / 128, 256, QKV_SMEM_BYTES>>>(x, qkv_w, qkv_b);
    k_attn<<<dim3(8, HEADS, NW), ATHREADS, ATTN_SMEM_BYTES>>>();
    k_proj<<<BATCH * NTOK / 128, 256>>>(proj_w, proj_b, out);
}

// round 5
// speedup vs baseline: 1.6545x; 1.0299x over previous
#include <cuda_runtime.h>
#include <cstdint>
#include <cstddef>

#define NTOK   98
#define CSTR   108
#define HEADS  4
#define DIM    128
#define BATCH  4096
#define NW     64
#define SCALE  0.17677669529663687f

__device__ float g_q[(size_t)BATCH * HEADS * NTOK * 32];
__device__ float g_k[(size_t)BATCH * HEADS * NTOK * 32];
__device__ float g_v[(size_t)BATCH * HEADS * NTOK * 32];
__device__ float g_o[(size_t)BATCH * NTOK * DIM];
__device__ float g_comb[(size_t)NW * HEADS * NTOK * CSTR];
__device__ float g_qkv_wr[384 * 128];
__device__ float g_proj_wr[128 * 128];

__device__ __forceinline__ float tf32r(float x) {
    unsigned u;
    asm("cvt.rna.tf32.f32 %0, %1;" : "=r"(u) : "f"(x));
    return __uint_as_float(u);
}
__device__ __forceinline__ float ex2f(float x) {
    float y;
    asm("ex2.approx.f32 %0, %1;" : "=f"(y) : "f"(x));
    return y;
}
__device__ __forceinline__ void mma8(float c[4], float a0, float a1, float a2, float a3,
                                     float b0, float b1) {
    asm volatile(
        "mma.sync.aligned.m16n8k8.row.col.f32.tf32.tf32.f32 "
        "{%0,%1,%2,%3},{%4,%5,%6,%7},{%8,%9},{%0,%1,%2,%3};\n"
        : "+f"(c[0]), "+f"(c[1]), "+f"(c[2]), "+f"(c[3])
        : "r"(__float_as_uint(a0)), "r"(__float_as_uint(a1)),
          "r"(__float_as_uint(a2)), "r"(__float_as_uint(a3)),
          "r"(__float_as_uint(b0)), "r"(__float_as_uint(b1)));
}
__device__ __forceinline__ void cp16(void* sptr, const void* gptr) {
    unsigned s = (unsigned)__cvta_generic_to_shared(sptr);
    asm volatile("cp.async.cg.shared.global [%0], [%1], 16;\n" :: "r"(s), "l"(gptr));
}
#define CP_COMMIT() asm volatile("cp.async.commit_group;\n" ::: "memory")
#define CP_WAIT0()  asm volatile("cp.async.wait_group 0;\n" ::: "memory")
#define CP_WAIT1()  asm volatile("cp.async.wait_group 1;\n" ::: "memory")

// ---------------- K-1: pre-round weights to tf32 ----------------
__global__ void k_prep(const float* __restrict__ qkv_w, const float* __restrict__ proj_w) {
    int i = blockIdx.x * 256 + threadIdx.x;
    if (i < 384 * 128) g_qkv_wr[i] = tf32r(qkv_w[i]);
    if (i < 128 * 128) g_proj_wr[i] = tf32r(proj_w[i]);
}

// ---------------- K0: comb = mask + gathered bias, padded ----------------
__global__ void k_comb(const float* __restrict__ mask,
                       const float* __restrict__ rpb,
                       const int* __restrict__ relidx) {
    const int w = blockIdx.x >> 2, h = blockIdx.x & 3;
    float* dst = g_comb + (size_t)(w * HEADS + h) * NTOK * CSTR;
    const float* msk = mask + (size_t)w * NTOK * NTOK;
    for (int idx = threadIdx.x; idx < NTOK * CSTR; idx += blockDim.x) {
        int i = idx / CSTR, j = idx - i * CSTR;
        float v = -10000.0f;
        if (j < NTOK) v = msk[i * NTOK + j] + rpb[relidx[i * NTOK + j] * HEADS + h];
        dst[idx] = v;
    }
}

// ---------------- K1: QKV GEMM, resident A, cp.async double-buffered B ----------------
#define QKV_SMEM_BYTES ((128 * 132 + 2 * 128 * 36) * 4)

__global__ void __launch_bounds__(256, 2) k_qkv(const float* __restrict__ x,
                                                const float* __restrict__ bias) {
    extern __shared__ float smq[];
    float (*As)[132] = reinterpret_cast<float(*)[132]>(smq);
    float* Bsbuf = smq + 128 * 132;                 // 2 x [128][36]
    const int m0 = blockIdx.x * 128;
    const int tid = threadIdx.x, lane = tid & 31, warp = tid >> 5;
    const int g = lane >> 2, tg = lane & 3;
    const int wm = warp >> 2, wn = warp & 3;
    const int fi = (tid & 7) * 4, r0 = tid >> 3;

    {   // load full 128x128 x tile once (rna-rounded)
        const int c = (tid & 31) * 4, rb = tid >> 5;
#pragma unroll
        for (int rr = 0; rr < 16; rr++) {
            int r = rb + rr * 8;
            float4 v4 = *reinterpret_cast<const float4*>(&x[(size_t)(m0 + r) * 128 + c]);
            *reinterpret_cast<float4*>(&As[r][c]) =
                make_float4(tf32r(v4.x), tf32r(v4.y), tf32r(v4.z), tf32r(v4.w));
        }
    }

    auto prefetchB = [&](int c, int buf) {
        const float* src = g_qkv_wr + (size_t)((c >> 2) * 128) * 128 + (c & 3) * 32;
        float* dst = Bsbuf + buf * (128 * 36);
#pragma unroll
        for (int rr = 0; rr < 4; rr++) {
            int r = r0 + rr * 32;
            cp16(&dst[r * 36 + fi], &src[(size_t)r * 128 + fi]);
        }
    };
    prefetchB(0, 0);
    CP_COMMIT();

    float c4[4][4][4];
    for (int c = 0; c < 12; c++) {
        const int kk = (c & 3) * 32;
        const float* Bs = Bsbuf + (c & 1) * (128 * 36);
        if ((c & 3) == 0) {
#pragma unroll
            for (int i = 0; i < 4; i++)
#pragma unroll
                for (int j = 0; j < 4; j++)
#pragma unroll
                    for (int q = 0; q < 4; q++) c4[i][j][q] = 0.f;
        }
        CP_WAIT0();
        __syncthreads();
        if (c + 1 < 12) { prefetchB(c + 1, (c + 1) & 1); CP_COMMIT(); }
#pragma unroll
        for (int ks = 0; ks < 32; ks += 8) {
            float a[4][4], bb[4][2];
#pragma unroll
            for (int mi = 0; mi < 4; mi++) {
                int rr = wm * 64 + mi * 16 + g;
                a[mi][0] = As[rr][kk + ks + tg];     a[mi][1] = As[rr + 8][kk + ks + tg];
                a[mi][2] = As[rr][kk + ks + tg + 4]; a[mi][3] = As[rr + 8][kk + ks + tg + 4];
            }
#pragma unroll
            for (int ni = 0; ni < 4; ni++) {
                int cc = wn * 32 + ni * 8 + g;
                bb[ni][0] = Bs[cc * 36 + ks + tg]; bb[ni][1] = Bs[cc * 36 + ks + tg + 4];
            }
#pragma unroll
            for (int mi = 0; mi < 4; mi++)
#pragma unroll
                for (int ni = 0; ni < 4; ni++)
                    mma8(c4[mi][ni], a[mi][0], a[mi][1], a[mi][2], a[mi][3],
                         bb[ni][0], bb[ni][1]);
        }
        __syncthreads();
        if ((c & 3) == 3) {   // epilogue for this n-tile
            int n0 = (c >> 2) * 128;
#pragma unroll
            for (int ni = 0; ni < 4; ni++) {
                int col = n0 + wn * 32 + ni * 8 + tg * 2;
                float b0 = bias[col], b1 = bias[col + 1];
                int sel = col >> 7, o = col & 127, h = o >> 5, d = o & 31;
                float* base = (sel == 0) ? g_q : ((sel == 1) ? g_k : g_v);
#pragma unroll
                for (int mi = 0; mi < 4; mi++) {
                    int m = m0 + wm * 64 + mi * 16 + g;
                    int b = m / NTOK, n = m - b * NTOK;
                    *reinterpret_cast<float2*>(&base[(((size_t)b * HEADS + h) * NTOK + n) * 32 + d]) =
                        make_float2(c4[mi][ni][0] + b0, c4[mi][ni][1] + b1);
                    int m2 = m + 8, b2 = m2 / NTOK, n2 = m2 - b2 * NTOK;
                    *reinterpret_cast<float2*>(&base[(((size_t)b2 * HEADS + h) * NTOK + n2) * 32 + d]) =
                        make_float2(c4[mi][ni][2] + b0, c4[mi][ni][3] + b1);
                }
            }
        }
    }
}

// ---------------- K2: fused attention, occ-3, single-buffer split-wait k/v ----------------
#define KSTR 36
#define VSTR 40
#define SM_KS (NTOK * CSTR)
#define SM_VS (SM_KS + 104 * KSTR)
#define ATTN_SMEM_BYTES ((SM_VS + 104 * VSTR) * 4)
#define ATHREADS 224

__global__ void __launch_bounds__(ATHREADS, 3) k_attn() {
    extern __shared__ float sm[];
    float* comb_s = sm;                 // [98][108]
    float* k_s = sm + SM_KS;            // [104][36]
    float* v_s = sm + SM_VS;            // [104][40]

    const int t = blockIdx.x, h = blockIdx.y, w = blockIdx.z;
    const int tid = threadIdx.x, lane = tid & 31, warp = tid >> 5;
    const int g = lane >> 2, tg = lane & 3;
    const int r1 = warp * 16 + g, r2 = r1 + 8;
    const int cr1 = min(r1, NTOK - 1), cr2 = min(r2, NTOK - 1);
    const unsigned FULL = 0xffffffffu;
    const int o1 = (lane & ~3) + (tg >> 1), o2 = o1 + 2;
    const bool el = (tg & 1);
    const float L2E = 1.4426950408889634f;

    {
        const float* cg = g_comb + (size_t)(w * HEADS + h) * NTOK * CSTR;
        for (int i = tid; i < NTOK * CSTR; i += ATHREADS) comb_s[i] = cg[i];
    }
    // zero pad rows 98..103 (cp.async never touches them)
    for (int i = tid; i < 6 * KSTR; i += ATHREADS) k_s[98 * KSTR + i] = 0.f;
    for (int i = tid; i < 6 * VSTR; i += ATHREADS) v_s[98 * VSTR + i] = 0.f;

    for (int jj = 0; jj < 8; jj++) {
        const int b = (t * 8 + jj) * NW + w;
        const size_t off = ((size_t)b * HEADS + h) * NTOK * 32;
        const float* gq = g_q + off;
        const float* gk = g_k + off;
        const float* gv = g_v + off;

        __syncthreads();            // prior iteration's reads done (also covers init)
        for (int i = tid; i < 784; i += ATHREADS) {     // K: 98 rows x 8 f4
            int r = i >> 3, f = (i & 7) * 4;
            cp16(&k_s[r * KSTR + f], &gk[r * 32 + f]);
        }
        CP_COMMIT();
        for (int i = tid; i < 784; i += ATHREADS) {     // V
            int r = i >> 3, f = (i & 7) * 4;
            cp16(&v_s[r * VSTR + f], &gv[r * 32 + f]);
        }
        CP_COMMIT();

        // q fragments from global — overlaps the K wait
        float qa[4][4];
#pragma unroll
        for (int ks4 = 0; ks4 < 4; ks4++) {
            qa[ks4][0] = qa[ks4][1] = qa[ks4][2] = qa[ks4][3] = 0.f;
            if (r1 < NTOK) {
                qa[ks4][0] = tf32r(gq[r1 * 32 + ks4 * 8 + tg] * SCALE);
                qa[ks4][2] = tf32r(gq[r1 * 32 + ks4 * 8 + tg + 4] * SCALE);
            }
            if (r2 < NTOK) {
                qa[ks4][1] = tf32r(gq[r2 * 32 + ks4 * 8 + tg] * SCALE);
                qa[ks4][3] = tf32r(gq[r2 * 32 + ks4 * 8 + tg + 4] * SCALE);
            }
        }
        CP_WAIT1();                 // K landed; V still in flight
        __syncthreads();

        // S = q @ k^T
        float s[13][4];
#pragma unroll
        for (int ni = 0; ni < 13; ni++)
            s[ni][0] = s[ni][1] = s[ni][2] = s[ni][3] = 0.f;
#pragma unroll
        for (int ks4 = 0; ks4 < 4; ks4++) {
#pragma unroll
            for (int ni = 0; ni < 13; ni++) {
                float b0 = k_s[(ni * 8 + g) * KSTR + ks4 * 8 + tg];
                float b1 = k_s[(ni * 8 + g) * KSTR + ks4 * 8 + tg + 4];
                mma8(s[ni], qa[ks4][0], qa[ks4][1], qa[ks4][2], qa[ks4][3], b0, b1);
            }
        }
        // bias + quad softmax
        float m1 = -1e30f, m2 = -1e30f;
#pragma unroll
        for (int ni = 0; ni < 13; ni++) {
            int c0 = ni * 8 + tg * 2;
            s[ni][0] += comb_s[cr1 * CSTR + c0];
            s[ni][1] += comb_s[cr1 * CSTR + c0 + 1];
            s[ni][2] += comb_s[cr2 * CSTR + c0];
            s[ni][3] += comb_s[cr2 * CSTR + c0 + 1];
            m1 = fmaxf(m1, fmaxf(s[ni][0], s[ni][1]));
            m2 = fmaxf(m2, fmaxf(s[ni][2], s[ni][3]));
        }
        m1 = fmaxf(m1, __shfl_xor_sync(FULL, m1, 1));
        m1 = fmaxf(m1, __shfl_xor_sync(FULL, m1, 2));
        m2 = fmaxf(m2, __shfl_xor_sync(FULL, m2, 1));
        m2 = fmaxf(m2, __shfl_xor_sync(FULL, m2, 2));
        float sum1 = 0.f, sum2 = 0.f;
#pragma unroll
        for (int ni = 0; ni < 13; ni++) {
            s[ni][0] = tf32r(ex2f((s[ni][0] - m1) * L2E));
            s[ni][1] = tf32r(ex2f((s[ni][1] - m1) * L2E));
            s[ni][2] = tf32r(ex2f((s[ni][2] - m2) * L2E));
            s[ni][3] = tf32r(ex2f((s[ni][3] - m2) * L2E));
            sum1 += s[ni][0] + s[ni][1];
            sum2 += s[ni][2] + s[ni][3];
        }
        sum1 += __shfl_xor_sync(FULL, sum1, 1);
        sum1 += __shfl_xor_sync(FULL, sum1, 2);
        sum2 += __shfl_xor_sync(FULL, sum2, 1);
        sum2 += __shfl_xor_sync(FULL, sum2, 2);
        float inv1 = 1.0f / sum1, inv2 = 1.0f / sum2;

        CP_WAIT0();                 // V landed (latency hidden behind S + softmax)
        __syncthreads();

        // O = P @ V, P transposed C->A layout via intra-quad shfl
        float o[4][4];
#pragma unroll
        for (int ni = 0; ni < 4; ni++) o[ni][0] = o[ni][1] = o[ni][2] = o[ni][3] = 0.f;
#pragma unroll
        for (int kt = 0; kt < 13; kt++) {
            float v00 = __shfl_sync(FULL, s[kt][0], o1);
            float v01 = __shfl_sync(FULL, s[kt][1], o1);
            float v02 = __shfl_sync(FULL, s[kt][2], o1);
            float v03 = __shfl_sync(FULL, s[kt][3], o1);
            float a0 = el ? v01 : v00;
            float a1 = el ? v03 : v02;
            float w00 = __shfl_sync(FULL, s[kt][0], o2);
            float w01 = __shfl_sync(FULL, s[kt][1], o2);
            float w02 = __shfl_sync(FULL, s[kt][2], o2);
            float w03 = __shfl_sync(FULL, s[kt][3], o2);
            float a2 = el ? w01 : w00;
            float a3 = el ? w03 : w02;
#pragma unroll
            for (int ni = 0; ni < 4; ni++) {
                float b0 = v_s[(kt * 8 + tg) * VSTR + ni * 8 + g];
                float b1 = v_s[(kt * 8 + tg + 4) * VSTR + ni * 8 + g];
                mma8(o[ni], a0, a1, a2, a3, b0, b1);
            }
        }
        // store normalized O, tf32-rounded so k_proj can cp.async it raw
        float* gob = g_o + (size_t)b * NTOK * DIM + h * 32;
#pragma unroll
        for (int ni = 0; ni < 4; ni++) {
            int d = ni * 8 + tg * 2;
            if (r1 < NTOK)
                *reinterpret_cast<float2*>(&gob[r1 * DIM + d]) =
                    make_float2(tf32r(o[ni][0] * inv1), tf32r(o[ni][1] * inv1));
            if (r2 < NTOK)
                *reinterpret_cast<float2*>(&gob[r2 * DIM + d]) =
                    make_float2(tf32r(o[ni][2] * inv2), tf32r(o[ni][3] * inv2));
        }
    }
}

// ---------------- K3: output projection, cp.async double-buffered A+B ----------------
#define PROJ_SMEM_BYTES (4 * 128 * 36 * 4)

__global__ void __launch_bounds__(256, 2) k_proj(const float* __restrict__ bias,
                                                 float* __restrict__ out) {
    extern __shared__ float smp[];
    float* Asb = smp;                   // 2 x [128][36]
    float* Bsb = smp + 2 * 128 * 36;    // 2 x [128][36]
    const int m0 = blockIdx.x * 128;
    const int tid = threadIdx.x, lane = tid & 31, warp = tid >> 5;
    const int g = lane >> 2, tg = lane & 3;
    const int wm = warp >> 2, wn = warp & 3;
    const int fi = (tid & 7) * 4, r0 = tid >> 3;

    auto prefetch = [&](int c, int buf) {
        const int kk = c * 32;
        float* ad = Asb + buf * (128 * 36);
        float* bd = Bsb + buf * (128 * 36);
#pragma unroll
        for (int rr = 0; rr < 4; rr++) {
            int r = r0 + rr * 32;
            cp16(&ad[r * 36 + fi], &g_o[(size_t)(m0 + r) * 128 + kk + fi]);
            cp16(&bd[r * 36 + fi], &g_proj_wr[(size_t)r * 128 + kk + fi]);
        }
    };
    prefetch(0, 0);
    CP_COMMIT();

    float c4[4][4][4];
#pragma unroll
    for (int i = 0; i < 4; i++)
#pragma unroll
        for (int j = 0; j < 4; j++)
#pragma unroll
            for (int q = 0; q < 4; q++) c4[i][j][q] = 0.f;

    for (int c = 0; c < 4; c++) {
        const float* As = Asb + (c & 1) * (128 * 36);
        const float* Bs = Bsb + (c & 1) * (128 * 36);
        CP_WAIT0();
        __syncthreads();
        if (c + 1 < 4) { prefetch(c + 1, (c + 1) & 1); CP_COMMIT(); }
#pragma unroll
        for (int ks = 0; ks < 32; ks += 8) {
            float a[4][4], bb[4][2];
#pragma unroll
            for (int mi = 0; mi < 4; mi++) {
                int rr = wm * 64 + mi * 16 + g;
                a[mi][0] = As[rr * 36 + ks + tg];     a[mi][1] = As[(rr + 8) * 36 + ks + tg];
                a[mi][2] = As[rr * 36 + ks + tg + 4]; a[mi][3] = As[(rr + 8) * 36 + ks + tg + 4];
            }
#pragma unroll
            for (int ni = 0; ni < 4; ni++) {
                int cc = wn * 32 + ni * 8 + g;
                bb[ni][0] = Bs[cc * 36 + ks + tg]; bb[ni][1] = Bs[cc * 36 + ks + tg + 4];
            }
#pragma unroll
            for (int mi = 0; mi < 4; mi++)
#pragma unroll
                for (int ni = 0; ni < 4; ni++)
                    mma8(c4[mi][ni], a[mi][0], a[mi][1], a[mi][2], a[mi][3],
                         bb[ni][0], bb[ni][1]);
        }
        __syncthreads();
    }
#pragma unroll
    for (int ni = 0; ni < 4; ni++) {
        int col = wn * 32 + ni * 8 + tg * 2;
        float b0 = bias[col], b1 = bias[col + 1];
#pragma unroll
        for (int mi = 0; mi < 4; mi++) {
            int m = m0 + wm * 64 + mi * 16 + g;
            *reinterpret_cast<float2*>(&out[(size_t)m * 128 + col]) =
                make_float2(c4[mi][ni][0] + b0, c4[mi][ni][1] + b1);
            *reinterpret_cast<float2*>(&out[(size_t)(m + 8) * 128 + col]) =
                make_float2(c4[mi][ni][2] + b0, c4[mi][ni][3] + b1);
        }
    }
}

extern "C" void kernel_launch(void* const* d_in, const int* in_sizes, int n_in,
                              void* d_out, int out_size) {
    const float* x      = (const float*)d_in[0];
    const float* mask   = (const float*)d_in[1];
    const float* rpb    = (const float*)d_in[2];
    const float* qkv_w  = (const float*)d_in[3];
    const float* qkv_b  = (const float*)d_in[4];
    const float* proj_w = (const float*)d_in[5];
    const float* proj_b = (const float*)d_in[6];
    const int*   relidx = (const int*)d_in[7];
    float* out = (float*)d_out;

    cudaFuncSetAttribute(k_qkv, cudaFuncAttributeMaxDynamicSharedMemorySize, QKV_SMEM_BYTES);
    cudaFuncSetAttribute(k_attn, cudaFuncAttributeMaxDynamicSharedMemorySize, ATTN_SMEM_BYTES);
    cudaFuncSetAttribute(k_proj, cudaFuncAttributeMaxDynamicSharedMemorySize, PROJ_SMEM_BYTES);

    k_prep<<<192, 256>>>(qkv_w, proj_w);
    k_comb<<<NW * HEADS, 256>>>(mask, rpb, relidx);
    k_qkv<<<BATCH * NTOK / 128, 256, QKV_SMEM_BYTES>>>(x, qkv_b);
    k_attn<<<dim3(8, HEADS, NW), ATHREADS, ATTN_SMEM_BYTES>>>();
    k_proj<<<BATCH * NTOK / 128, 256, PROJ_SMEM_BYTES>>>(proj_b, out);
}